// round 13
// baseline (speedup 1.0000x reference)
#include <cuda_runtime.h>
#include <cuda_bf16.h>
#include <math.h>
#include <stdint.h>

#define BB   2
#define TT   2048
#define DIM  2048
#define NH   16
#define HD   128
#define MTOT (BB*TT)
#define K3   6144
#define SCALE_QK 0.08838834764831843f
#define SOFTCAP 30.0f

// ---------------- scratch ----------------
__device__ float g_op[MTOT * DIM];
__device__ float g_gl[MTOT * DIM];
__device__ __nv_bfloat16 g_xnb[(size_t)MTOT * DIM];     // plain bf16 xn
__device__ __nv_bfloat16 g_x3 [(size_t)MTOT * K3];      // [hi|hi|lo]
__device__ __nv_bfloat16 g_at3[(size_t)MTOT * K3];      // [hi|hi|lo]
__device__ __nv_bfloat16 g_w3[2][(size_t)DIM * K3];     // Wo, gW  [hi|lo|hi]
__device__ __nv_bfloat16 g_wb[3][(size_t)DIM * DIM];    // Wq,Wk,Wv plain bf16
__device__ __nv_bfloat16 g_qb[(size_t)MTOT * DIM];      // [b,t,h*d] bf16
__device__ __nv_bfloat16 g_kb[(size_t)MTOT * DIM];
__device__ __nv_bfloat16 g_vb[(size_t)MTOT * DIM];

// ---------------- helpers ----------------
__device__ __forceinline__ uint32_t smem_u32(const void* p) {
    uint32_t a;
    asm("{ .reg .u64 t; cvta.to.shared.u64 t, %1; cvt.u32.u64 %0, t; }" : "=r"(a) : "l"(p));
    return a;
}

#define LDSM_X4(r0, r1, r2, r3, a) \
    asm volatile("ldmatrix.sync.aligned.m8n8.x4.shared.b16 {%0,%1,%2,%3}, [%4];" \
        : "=r"(r0), "=r"(r1), "=r"(r2), "=r"(r3) : "r"(a))
#define LDSM_X4_T(r0, r1, r2, r3, a) \
    asm volatile("ldmatrix.sync.aligned.m8n8.x4.trans.shared.b16 {%0,%1,%2,%3}, [%4];" \
        : "=r"(r0), "=r"(r1), "=r"(r2), "=r"(r3) : "r"(a))
#define MMA_BF16(c, a0, a1, a2, a3, b0, b1) \
    asm volatile("mma.sync.aligned.m16n8k16.row.col.f32.bf16.bf16.f32 " \
        "{%0,%1,%2,%3}, {%4,%5,%6,%7}, {%8,%9}, {%0,%1,%2,%3};" \
        : "+f"((c)[0]), "+f"((c)[1]), "+f"((c)[2]), "+f"((c)[3]) \
        : "r"(a0), "r"(a1), "r"(a2), "r"(a3), "r"(b0), "r"(b1))

__device__ __forceinline__ void bsplit(float v, unsigned short &h, unsigned short &l) {
    __nv_bfloat16 hb = __float2bfloat16_rn(v);
    __nv_bfloat16 lb = __float2bfloat16_rn(v - __bfloat162float(hb));
    h = __bfloat16_as_ushort(hb);
    l = __bfloat16_as_ushort(lb);
}
__device__ __forceinline__ uint32_t packbf(float lo, float hi) {
    __nv_bfloat162 b = __floats2bfloat162_rn(lo, hi);
    return *(uint32_t*)&b;
}
__device__ __forceinline__ unsigned short b16(float v) {
    return __bfloat16_as_ushort(__float2bfloat16_rn(v));
}

// ------------- RMSNorm -> plain bf16 xn -------------
__global__ __launch_bounds__(256)
void rmsnorm_bf16_kernel(const float* __restrict__ x, const float* __restrict__ w)
{
    const int row = blockIdx.x;
    const int tid = threadIdx.x;
    const float4* xr = (const float4*)(x + (size_t)row * DIM);
    float4 v0 = xr[tid];
    float4 v1 = xr[tid + 256];
    float s = v0.x*v0.x + v0.y*v0.y + v0.z*v0.z + v0.w*v0.w
            + v1.x*v1.x + v1.y*v1.y + v1.z*v1.z + v1.w*v1.w;
    #pragma unroll
    for (int o = 16; o > 0; o >>= 1) s += __shfl_xor_sync(0xffffffffu, s, o);
    __shared__ float red[8];
    if ((tid & 31) == 0) red[tid >> 5] = s;
    __syncthreads();
    float tot = red[0]+red[1]+red[2]+red[3]+red[4]+red[5]+red[6]+red[7];
    float r = rsqrtf(tot * (1.0f / (float)DIM) + 1e-6f);
    const float4* wr = (const float4*)w;
    float4 w0 = wr[tid], w1 = wr[tid + 256];
    unsigned short* ob = (unsigned short*)g_xnb + (size_t)row * DIM;
    *(ushort4*)(ob + tid * 4) =
        make_ushort4(b16(v0.x*r*w0.x), b16(v0.y*r*w0.y), b16(v0.z*r*w0.z), b16(v0.w*r*w0.w));
    *(ushort4*)(ob + (tid + 256) * 4) =
        make_ushort4(b16(v1.x*r*w1.x), b16(v1.y*r*w1.y), b16(v1.z*r*w1.z), b16(v1.w*r*w1.w));
}

// ------------- 3-term split conversion: [R,2048] fp32 -> [R,6144] bf16 -------------
// modeA=1: [hi|hi|lo]   modeA=0: [hi|lo|hi]
__global__ __launch_bounds__(256)
void convert_split_kernel(const float* __restrict__ in, __nv_bfloat16* __restrict__ out, int modeA)
{
    int idx = blockIdx.x * 256 + threadIdx.x;
    float4 v = ((const float4*)in)[idx];
    int r = idx >> 9, c = (idx & 511) * 4;
    unsigned short h[4], l[4];
    bsplit(v.x, h[0], l[0]); bsplit(v.y, h[1], l[1]);
    bsplit(v.z, h[2], l[2]); bsplit(v.w, h[3], l[3]);
    ushort4 hs = make_ushort4(h[0], h[1], h[2], h[3]);
    ushort4 ls = make_ushort4(l[0], l[1], l[2], l[3]);
    unsigned short* ob = (unsigned short*)out + (size_t)r * K3 + c;
    *(ushort4*)(ob)        = hs;
    *(ushort4*)(ob + 2048) = modeA ? hs : ls;
    *(ushort4*)(ob + 4096) = modeA ? ls : hs;
}

// ------------- weight plain bf16 conversion: fp32 [n,2048] -> bf16 [n,2048] -------------
__global__ __launch_bounds__(256)
void convert_wb_kernel(const float* __restrict__ w0, const float* __restrict__ w1,
                       const float* __restrict__ w2)
{
    const float* in = (blockIdx.y == 0) ? w0 : (blockIdx.y == 1) ? w1 : w2;
    unsigned short* out = (unsigned short*)(g_wb[0] + (size_t)blockIdx.y * DIM * DIM);
    int idx = blockIdx.x * 256 + threadIdx.x;
    float4 v = ((const float4*)in)[idx];
    *(ushort4*)(out + idx * 4) = make_ushort4(b16(v.x), b16(v.y), b16(v.z), b16(v.w));
}

// ================= HMMA bf16 GEMM =================
#define BM 128
#define BN 128
#define BK 64
#define GSTAGES 3
#define CHUNK_BYTES (BM*128 + BN*128)       // 32768
#define GEMM_SMEM (GSTAGES * CHUNK_BYTES + 1024)

// fp32-out version (3-term operands, KS = 6144):
template<int KS>
__global__ __launch_bounds__(256, 2)
void mma_gemm_kernel(const __nv_bfloat16* __restrict__ A,
                     const __nv_bfloat16* __restrict__ B,
                     float* __restrict__ C, int N)
{
    extern __shared__ char dynsm[];
    const uint32_t sb = (smem_u32(dynsm) + 1023u) & ~1023u;
    const int tid = threadIdx.x;
    const int w = tid >> 5, lane = tid & 31;
    const int wm = (w >> 2) * 64, wn = (w & 3) * 32;
    const int NCHUNK = KS / BK;

    const int mBase = blockIdx.y * BM;
    const int nBase = blockIdx.x * BN;
    const __nv_bfloat16* Ab = A + (size_t)mBase * KS;
    const __nv_bfloat16* Bb = B + (size_t)nBase * KS;

    float acc[4][4][4];
    #pragma unroll
    for (int i = 0; i < 4; i++)
        #pragma unroll
        for (int j = 0; j < 4; j++)
            #pragma unroll
            for (int q = 0; q < 4; q++) acc[i][j][q] = 0.f;

    auto load_chunk = [&](int c, int stage) {
        uint32_t abase = sb + stage * CHUNK_BYTES;
        uint32_t bbase = abase + BM * 128;
        #pragma unroll
        for (int t = 0; t < 8; t++) {
            int o = tid + t * 256;
            const __nv_bfloat16* src;
            uint32_t base;
            int row, c16;
            if (o < 1024) {
                row = o >> 3; c16 = o & 7;
                src = Ab + (size_t)row * KS + c * 64 + c16 * 8;
                base = abase;
            } else {
                int ob = o - 1024;
                row = ob >> 3; c16 = ob & 7;
                src = Bb + (size_t)row * KS + c * 64 + c16 * 8;
                base = bbase;
            }
            uint32_t off = (uint32_t)(row * 128 + c16 * 16);
            uint32_t dst = base + (off ^ ((off >> 3) & 0x70));
            asm volatile("cp.async.cg.shared.global [%0], [%1], 16;" :: "r"(dst), "l"(src) : "memory");
        }
        asm volatile("cp.async.commit_group;" ::: "memory");
    };

    load_chunk(0, 0);
    load_chunk(1, 1);

    const int rowadd = (lane & 7) + ((lane >> 3) & 1) * 8;
    const int colmi  = (lane >> 4) * 16;

    #pragma unroll 1
    for (int c = 0; c < NCHUNK; c++) {
        asm volatile("cp.async.wait_group %0;" :: "n"(1));
        __syncthreads();
        if (c + 2 < NCHUNK) load_chunk(c + 2, (c + 2) % GSTAGES);
        else asm volatile("cp.async.commit_group;" ::: "memory");

        uint32_t abase = sb + (c % GSTAGES) * CHUNK_BYTES;
        uint32_t bbase = abase + BM * 128;

        #pragma unroll
        for (int s = 0; s < 4; s++) {
            const int colb = s * 32 + colmi;
            uint32_t af[4][4];
            #pragma unroll
            for (int i = 0; i < 4; i++) {
                uint32_t off = (uint32_t)((wm + i * 16 + rowadd) * 128 + colb);
                LDSM_X4(af[i][0], af[i][1], af[i][2], af[i][3], abase + (off ^ ((off >> 3) & 0x70)));
            }
            uint32_t bf[2][4];
            #pragma unroll
            for (int j = 0; j < 2; j++) {
                uint32_t off = (uint32_t)((wn + j * 16 + rowadd) * 128 + colb);
                LDSM_X4(bf[j][0], bf[j][1], bf[j][2], bf[j][3], bbase + (off ^ ((off >> 3) & 0x70)));
            }
            #pragma unroll
            for (int i = 0; i < 4; i++)
                #pragma unroll
                for (int j = 0; j < 2; j++)
                    #pragma unroll
                    for (int ns = 0; ns < 2; ns++)
                        MMA_BF16(acc[i][j * 2 + ns],
                                 af[i][0], af[i][1], af[i][2], af[i][3],
                                 bf[j][ns], bf[j][2 + ns]);
        }
    }

    const int gid = lane >> 2, ctg = lane & 3;
    float* Cw = C + (size_t)(mBase + wm + gid) * N + nBase + wn + ctg * 2;
    #pragma unroll
    for (int i = 0; i < 4; i++)
        #pragma unroll
        for (int jn = 0; jn < 4; jn++) {
            float* p = Cw + (size_t)(i * 16) * N + jn * 8;
            *(float2*)p             = make_float2(acc[i][jn][0], acc[i][jn][1]);
            *(float2*)(p + 8 * N)   = make_float2(acc[i][jn][2], acc[i][jn][3]);
        }
}

// ---- merged QKV GEMM (K=2048 plain bf16, grid.z selects weight), bf16 row-major epilogue ----
__global__ __launch_bounds__(256, 2)
void mma_gemm_qkv_kernel()
{
    extern __shared__ char dynsm[];
    const uint32_t sb = (smem_u32(dynsm) + 1023u) & ~1023u;
    const int tid = threadIdx.x;
    const int w = tid >> 5, lane = tid & 31;
    const int wm = (w >> 2) * 64, wn = (w & 3) * 32;
    const int NCHUNK = DIM / BK;   // 32

    const int sel   = blockIdx.z;
    const int mBase = blockIdx.y * BM;
    const int nBase = blockIdx.x * BN;
    const __nv_bfloat16* Ab = g_xnb + (size_t)mBase * DIM;
    const __nv_bfloat16* Bb = g_wb[0] + (size_t)sel * DIM * DIM + (size_t)nBase * DIM;

    float acc[4][4][4];
    #pragma unroll
    for (int i = 0; i < 4; i++)
        #pragma unroll
        for (int j = 0; j < 4; j++)
            #pragma unroll
            for (int q = 0; q < 4; q++) acc[i][j][q] = 0.f;

    auto load_chunk = [&](int c, int stage) {
        uint32_t abase = sb + stage * CHUNK_BYTES;
        uint32_t bbase = abase + BM * 128;
        #pragma unroll
        for (int t = 0; t < 8; t++) {
            int o = tid + t * 256;
            const __nv_bfloat16* src;
            uint32_t base;
            int row, c16;
            if (o < 1024) {
                row = o >> 3; c16 = o & 7;
                src = Ab + (size_t)row * DIM + c * 64 + c16 * 8;
                base = abase;
            } else {
                int ob = o - 1024;
                row = ob >> 3; c16 = ob & 7;
                src = Bb + (size_t)row * DIM + c * 64 + c16 * 8;
                base = bbase;
            }
            uint32_t off = (uint32_t)(row * 128 + c16 * 16);
            uint32_t dst = base + (off ^ ((off >> 3) & 0x70));
            asm volatile("cp.async.cg.shared.global [%0], [%1], 16;" :: "r"(dst), "l"(src) : "memory");
        }
        asm volatile("cp.async.commit_group;" ::: "memory");
    };

    load_chunk(0, 0);
    load_chunk(1, 1);

    const int rowadd = (lane & 7) + ((lane >> 3) & 1) * 8;
    const int colmi  = (lane >> 4) * 16;

    #pragma unroll 1
    for (int c = 0; c < NCHUNK; c++) {
        asm volatile("cp.async.wait_group %0;" :: "n"(1));
        __syncthreads();
        if (c + 2 < NCHUNK) load_chunk(c + 2, (c + 2) % GSTAGES);
        else asm volatile("cp.async.commit_group;" ::: "memory");

        uint32_t abase = sb + (c % GSTAGES) * CHUNK_BYTES;
        uint32_t bbase = abase + BM * 128;

        #pragma unroll
        for (int s = 0; s < 4; s++) {
            const int colb = s * 32 + colmi;
            uint32_t af[4][4];
            #pragma unroll
            for (int i = 0; i < 4; i++) {
                uint32_t off = (uint32_t)((wm + i * 16 + rowadd) * 128 + colb);
                LDSM_X4(af[i][0], af[i][1], af[i][2], af[i][3], abase + (off ^ ((off >> 3) & 0x70)));
            }
            uint32_t bf[2][4];
            #pragma unroll
            for (int j = 0; j < 2; j++) {
                uint32_t off = (uint32_t)((wn + j * 16 + rowadd) * 128 + colb);
                LDSM_X4(bf[j][0], bf[j][1], bf[j][2], bf[j][3], bbase + (off ^ ((off >> 3) & 0x70)));
            }
            #pragma unroll
            for (int i = 0; i < 4; i++)
                #pragma unroll
                for (int j = 0; j < 2; j++)
                    #pragma unroll
                    for (int ns = 0; ns < 2; ns++)
                        MMA_BF16(acc[i][j * 2 + ns],
                                 af[i][0], af[i][1], af[i][2], af[i][3],
                                 bf[j][ns], bf[j][2 + ns]);
        }
    }

    // bf16 row-major epilogue into [b,t,h*d]
    unsigned short* outp = (unsigned short*)(sel == 0 ? g_qb : sel == 1 ? g_kb : g_vb);
    const int gid = lane >> 2, ctg = lane & 3;
    unsigned short* Cw = outp + (size_t)(mBase + wm + gid) * DIM + nBase + wn + ctg * 2;
    #pragma unroll
    for (int i = 0; i < 4; i++)
        #pragma unroll
        for (int jn = 0; jn < 4; jn++) {
            unsigned short* p = Cw + (size_t)(i * 16) * DIM + jn * 8;
            *(ushort2*)p               = make_ushort2(b16(acc[i][jn][0]), b16(acc[i][jn][1]));
            *(ushort2*)(p + 8 * DIM)   = make_ushort2(b16(acc[i][jn][2]), b16(acc[i][jn][3]));
        }
}

// ------------- HMMA causal softcapped flash attention (BQ=128, BK=64) -------------
// reads bf16 [b,t,h*d] (row stride DIM, head offset h*HD)
#define AST 136
#define KV_BYTES (2 * 64 * AST * 2)
#define ATT2_SMEM (128 * AST * 2 + 2 * KV_BYTES)

__global__ __launch_bounds__(256)
void attn_mma_kernel(const __nv_bfloat16* __restrict__ Qg,
                     const __nv_bfloat16* __restrict__ Kg,
                     const __nv_bfloat16* __restrict__ Vg)
{
    extern __shared__ char smraw[];
    const uint32_t sQ  = smem_u32(smraw);
    const uint32_t sKV = sQ + 128 * AST * 2;

    const int tid = threadIdx.x;
    const int w = tid >> 5, lane = tid & 31;
    const int qt = (int)gridDim.x - 1 - (int)blockIdx.x;
    const int h  = blockIdx.y;
    const int b  = blockIdx.z;

    const __nv_bfloat16* Qb = Qg + (size_t)(b * TT + qt * 128) * DIM + h * HD;
    const __nv_bfloat16* Kb = Kg + (size_t)(b * TT) * DIM + h * HD;
    const __nv_bfloat16* Vb = Vg + (size_t)(b * TT) * DIM + h * HD;

    #pragma unroll
    for (int t = 0; t < 8; t++) {
        int ch = tid + t * 256;
        int row = ch >> 4, c16 = ch & 15;
        uint32_t dst = sQ + row * 272 + c16 * 16;
        const __nv_bfloat16* src = Qb + (size_t)row * DIM + c16 * 8;
        asm volatile("cp.async.cg.shared.global [%0], [%1], 16;" :: "r"(dst), "l"(src) : "memory");
    }
    asm volatile("cp.async.commit_group;" ::: "memory");

    auto loadKV = [&](int kt, int stage) {
        uint32_t base = sKV + stage * KV_BYTES;
        const __nv_bfloat16* Kt = Kb + (size_t)kt * 64 * DIM;
        const __nv_bfloat16* Vt = Vb + (size_t)kt * 64 * DIM;
        #pragma unroll
        for (int t = 0; t < 8; t++) {
            int ch = tid + t * 256;
            int row = (ch >> 4) & 63, c16 = ch & 15;
            bool isV = ch >= 1024;
            const __nv_bfloat16* src = (isV ? Vt : Kt) + (size_t)row * DIM + c16 * 8;
            uint32_t dst = base + (isV ? (64u * 272u) : 0u) + row * 272 + c16 * 16;
            asm volatile("cp.async.cg.shared.global [%0], [%1], 16;" :: "r"(dst), "l"(src) : "memory");
        }
        asm volatile("cp.async.commit_group;" ::: "memory");
    };

    const int numK = 2 * qt + 2;
    loadKV(0, 0);
    loadKV(1, 1);

    float oacc[16][4];
    #pragma unroll
    for (int j = 0; j < 16; j++)
        #pragma unroll
        for (int q = 0; q < 4; q++) oacc[j][q] = 0.f;
    float den0 = 0.f, den1 = 0.f;

    const int rowadd = (lane & 7) + ((lane >> 3) & 1) * 8;
    const int colmi  = (lane >> 4) * 16;
    const int colq   = (lane & 3) * 2;
    const int rr0    = qt * 128 + w * 16 + (lane >> 2);

    #pragma unroll 1
    for (int kt = 0; kt < numK; kt++) {
        asm volatile("cp.async.wait_group %0;" :: "n"(1));
        __syncthreads();
        const uint32_t sK = sKV + (kt & 1) * KV_BYTES;
        const uint32_t sV = sK + 64u * 272u;

        float cs[8][4];
        #pragma unroll
        for (int j = 0; j < 8; j++)
            #pragma unroll
            for (int q = 0; q < 4; q++) cs[j][q] = 0.f;

        #pragma unroll
        for (int s = 0; s < 8; s++) {
            uint32_t a0, a1, a2, a3;
            LDSM_X4(a0, a1, a2, a3, sQ + (w * 16 + rowadd) * 272 + s * 32 + colmi);
            #pragma unroll
            for (int g = 0; g < 4; g++) {
                uint32_t k0, k1, k2, k3;
                LDSM_X4(k0, k1, k2, k3, sK + (g * 16 + rowadd) * 272 + s * 32 + colmi);
                MMA_BF16(cs[2*g],   a0, a1, a2, a3, k0, k2);
                MMA_BF16(cs[2*g+1], a0, a1, a2, a3, k1, k3);
            }
        }

        const bool msk = (kt >= 2 * qt);
        #pragma unroll
        for (int j = 0; j < 8; j++) {
            const int cb = kt * 64 + j * 8 + colq;
            #pragma unroll
            for (int q = 0; q < 4; q++) {
                float sv = cs[j][q] * SCALE_QK;
                float xx = sv * (1.0f / SOFTCAP);
                float x2 = xx * xx;
                float capped;
                if (fabsf(xx) > 0.55f) capped = SOFTCAP * tanhf(xx);
                else capped = sv * (1.0f - x2 * (0.33333334f - x2 * (0.13333334f - x2 * 0.05396825f)));
                float p = __expf(capped);
                if (msk) {
                    int col = cb + (q & 1);
                    int rowg = rr0 + (q >> 1) * 8;
                    if (col > rowg) p = 0.f;
                }
                cs[j][q] = p;
                if (q >> 1) den1 += p; else den0 += p;
            }
        }

        uint32_t pa[4][4];
        #pragma unroll
        for (int kk = 0; kk < 4; kk++) {
            pa[kk][0] = packbf(cs[2*kk][0],   cs[2*kk][1]);
            pa[kk][1] = packbf(cs[2*kk][2],   cs[2*kk][3]);
            pa[kk][2] = packbf(cs[2*kk+1][0], cs[2*kk+1][1]);
            pa[kk][3] = packbf(cs[2*kk+1][2], cs[2*kk+1][3]);
        }

        #pragma unroll
        for (int kk = 0; kk < 4; kk++) {
            #pragma unroll
            for (int g = 0; g < 8; g++) {
                uint32_t v0, v1, v2, v3;
                LDSM_X4_T(v0, v1, v2, v3, sV + (kk * 16 + rowadd) * 272 + g * 32 + colmi);
                MMA_BF16(oacc[2*g],   pa[kk][0], pa[kk][1], pa[kk][2], pa[kk][3], v0, v1);
                MMA_BF16(oacc[2*g+1], pa[kk][0], pa[kk][1], pa[kk][2], pa[kk][3], v2, v3);
            }
        }

        __syncthreads();
        if (kt + 2 < numK) loadKV(kt + 2, kt & 1);
        else asm volatile("cp.async.commit_group;" ::: "memory");
    }

    den0 += __shfl_xor_sync(0xffffffffu, den0, 1);
    den0 += __shfl_xor_sync(0xffffffffu, den0, 2);
    den1 += __shfl_xor_sync(0xffffffffu, den1, 1);
    den1 += __shfl_xor_sync(0xffffffffu, den1, 2);
    const float i0 = 1.0f / den0, i1 = 1.0f / den1;

    const int t0 = qt * 128 + w * 16 + (lane >> 2);
    unsigned short* outb = (unsigned short*)g_at3;
    size_t base0 = ((size_t)(b * TT + t0)) * K3 + h * 128 + colq;
    size_t base1 = base0 + (size_t)8 * K3;
    #pragma unroll
    for (int j = 0; j < 16; j++) {
        float p0 = oacc[j][0] * i0, p1 = oacc[j][1] * i0;
        float p2 = oacc[j][2] * i1, p3 = oacc[j][3] * i1;
        unsigned short h0, l0, h1, l1, h2, l2, h3, l3;
        bsplit(p0, h0, l0); bsplit(p1, h1, l1);
        bsplit(p2, h2, l2); bsplit(p3, h3, l3);
        unsigned short* q0 = outb + base0 + j * 8;
        unsigned short* q1 = outb + base1 + j * 8;
        *(ushort2*)(q0)        = make_ushort2(h0, h1);
        *(ushort2*)(q0 + 2048) = make_ushort2(h0, h1);
        *(ushort2*)(q0 + 4096) = make_ushort2(l0, l1);
        *(ushort2*)(q1)        = make_ushort2(h2, h3);
        *(ushort2*)(q1 + 2048) = make_ushort2(h2, h3);
        *(ushort2*)(q1 + 4096) = make_ushort2(l2, l3);
    }
}

// ---------------------------- gate + residual blend ---------------------------
__global__ __launch_bounds__(256)
void blend_kernel(const float* __restrict__ x, const float* __restrict__ gb,
                  float* __restrict__ out)
{
    const int i4 = blockIdx.x * 256 + threadIdx.x;
    const int col4 = i4 & 511;
    float4 xv = ((const float4*)x)[i4];
    float4 ov = ((const float4*)g_op)[i4];
    float4 gv = ((const float4*)g_gl)[i4];
    float4 bv = ((const float4*)gb)[col4];
    float a0 = 1.0f / (1.0f + __expf(-(gv.x + bv.x)));
    float a1 = 1.0f / (1.0f + __expf(-(gv.y + bv.y)));
    float a2 = 1.0f / (1.0f + __expf(-(gv.z + bv.z)));
    float a3 = 1.0f / (1.0f + __expf(-(gv.w + bv.w)));
    float4 r;
    r.x = xv.x + a0 * (ov.x - xv.x);
    r.y = xv.y + a1 * (ov.y - xv.y);
    r.z = xv.z + a2 * (ov.z - xv.z);
    r.w = xv.w + a3 * (ov.w - xv.w);
    ((float4*)out)[i4] = r;
}

// ----------------------------------- launch -----------------------------------
extern "C" void kernel_launch(void* const* d_in, const int* in_sizes, int n_in,
                              void* d_out, int out_size)
{
    (void)in_sizes; (void)n_in; (void)out_size;
    const float* x   = (const float*)d_in[0];
    const float* Wq  = (const float*)d_in[2];
    const float* Wk  = (const float*)d_in[3];
    const float* Wv  = (const float*)d_in[4];
    const float* Wo  = (const float*)d_in[5];
    const float* lnw = (const float*)d_in[6];
    const float* gW  = (const float*)d_in[7];
    const float* gb  = (const float*)d_in[8];
    float* out = (float*)d_out;

    static int attr_set = 0;
    static cudaStream_t s1 = nullptr;
    static cudaEvent_t evFork = nullptr, evJoin = nullptr;
    if (!attr_set) {
        cudaFuncSetAttribute(mma_gemm_kernel<K3>, cudaFuncAttributeMaxDynamicSharedMemorySize, GEMM_SMEM);
        cudaFuncSetAttribute(mma_gemm_qkv_kernel, cudaFuncAttributeMaxDynamicSharedMemorySize, GEMM_SMEM);
        cudaFuncSetAttribute(attn_mma_kernel,     cudaFuncAttributeMaxDynamicSharedMemorySize, ATT2_SMEM);
        cudaStreamCreateWithFlags(&s1, cudaStreamNonBlocking);
        cudaEventCreateWithFlags(&evFork, cudaEventDisableTiming);
        cudaEventCreateWithFlags(&evJoin, cudaEventDisableTiming);
        attr_set = 1;
    }

    void *pop, *pgl, *px3, *pat3, *pw3, *pqb, *pkb, *pvb;
    cudaGetSymbolAddress(&pop, g_op);
    cudaGetSymbolAddress(&pgl, g_gl);
    cudaGetSymbolAddress(&px3,  g_x3);
    cudaGetSymbolAddress(&pat3, g_at3);
    cudaGetSymbolAddress(&pw3,  g_w3);
    cudaGetSymbolAddress(&pqb, g_qb);
    cudaGetSymbolAddress(&pkb, g_kb);
    cudaGetSymbolAddress(&pvb, g_vb);
    __nv_bfloat16* w3 = (__nv_bfloat16*)pw3;
    const size_t WSTRIDE3 = (size_t)DIM * K3;

    dim3 gGemm(DIM / BN, MTOT / BM);        // (16, 32)

    // ---- fork side stream: x3, gW, Wo conversions + gate GEMM ----
    cudaEventRecord(evFork, 0);
    cudaStreamWaitEvent(s1, evFork, 0);

    convert_split_kernel<<<(MTOT * (DIM/4)) / 256, 256, 0, s1>>>(x, (__nv_bfloat16*)px3, 1);
    convert_split_kernel<<<(DIM  * (DIM/4)) / 256, 256, 0, s1>>>(gW, w3 + 1 * WSTRIDE3, 0);
    convert_split_kernel<<<(DIM  * (DIM/4)) / 256, 256, 0, s1>>>(Wo, w3 + 0 * WSTRIDE3, 0);
    mma_gemm_kernel<K3><<<gGemm, 256, GEMM_SMEM, s1>>>((const __nv_bfloat16*)px3, w3 + 1 * WSTRIDE3, (float*)pgl, DIM);
    cudaEventRecord(evJoin, s1);

    // ---- main stream: rmsnorm -> merged QKV GEMM (K=2048) -> attention -> Wo ----
    rmsnorm_bf16_kernel<<<MTOT, 256>>>(x, lnw);
    dim3 gWb((DIM * (DIM/4)) / 256, 3);
    convert_wb_kernel<<<gWb, 256>>>(Wq, Wk, Wv);

    dim3 gQKV(DIM / BN, MTOT / BM, 3);      // (16, 32, 3)
    mma_gemm_qkv_kernel<<<gQKV, 256, GEMM_SMEM>>>();

    dim3 gAttn(TT / 128, NH, BB);           // (16, 16, 2)
    attn_mma_kernel<<<gAttn, 256, ATT2_SMEM>>>((const __nv_bfloat16*)pqb,
                                               (const __nv_bfloat16*)pkb,
                                               (const __nv_bfloat16*)pvb);

    // join side stream (covers gate GEMM), then Wo GEMM + blend
    cudaStreamWaitEvent(0, evJoin, 0);
    mma_gemm_kernel<K3><<<gGemm, 256, GEMM_SMEM>>>((const __nv_bfloat16*)pat3, w3 + 0 * WSTRIDE3, (float*)pop, DIM);

    blend_kernel<<<(MTOT * DIM / 4) / 256, 256>>>(x, gb, out);
}

// round 15
// speedup vs baseline: 1.6109x; 1.6109x over previous
#include <cuda_runtime.h>
#include <cuda_bf16.h>
#include <math.h>
#include <stdint.h>

#define BB   2
#define TT   2048
#define DIM  2048
#define NH   16
#define HD   128
#define MTOT (BB*TT)
#define K3   6144
#define SCALE_QK 0.08838834764831843f
#define SOFTCAP 30.0f

// ---------------- scratch ----------------
__device__ float g_op[MTOT * DIM];
__device__ float g_gl[MTOT * DIM];
__device__ __nv_bfloat16 g_xnb[(size_t)MTOT * DIM];     // plain bf16 xn
__device__ __nv_bfloat16 g_x3 [(size_t)MTOT * K3];      // [hi|hi|lo]
__device__ __nv_bfloat16 g_at3[(size_t)MTOT * K3];      // [hi|hi|lo]
__device__ __nv_bfloat16 g_w3[2][(size_t)DIM * K3];     // Wo, gW  [hi|lo|hi]
__device__ __nv_bfloat16 g_wb[3][(size_t)DIM * DIM];    // Wq,Wk,Wv plain bf16
__device__ __nv_bfloat16 g_qb[(size_t)MTOT * DIM];      // [b,t,h*d] bf16
__device__ __nv_bfloat16 g_kb[(size_t)MTOT * DIM];
__device__ __nv_bfloat16 g_vb[(size_t)MTOT * DIM];

// ---------------- helpers ----------------
__device__ __forceinline__ uint32_t smem_u32(const void* p) {
    uint32_t a;
    asm("{ .reg .u64 t; cvta.to.shared.u64 t, %1; cvt.u32.u64 %0, t; }" : "=r"(a) : "l"(p));
    return a;
}

#define LDSM_X4(r0, r1, r2, r3, a) \
    asm volatile("ldmatrix.sync.aligned.m8n8.x4.shared.b16 {%0,%1,%2,%3}, [%4];" \
        : "=r"(r0), "=r"(r1), "=r"(r2), "=r"(r3) : "r"(a))
#define LDSM_X4_T(r0, r1, r2, r3, a) \
    asm volatile("ldmatrix.sync.aligned.m8n8.x4.trans.shared.b16 {%0,%1,%2,%3}, [%4];" \
        : "=r"(r0), "=r"(r1), "=r"(r2), "=r"(r3) : "r"(a))
#define MMA_BF16(c, a0, a1, a2, a3, b0, b1) \
    asm volatile("mma.sync.aligned.m16n8k16.row.col.f32.bf16.bf16.f32 " \
        "{%0,%1,%2,%3}, {%4,%5,%6,%7}, {%8,%9}, {%0,%1,%2,%3};" \
        : "+f"((c)[0]), "+f"((c)[1]), "+f"((c)[2]), "+f"((c)[3]) \
        : "r"(a0), "r"(a1), "r"(a2), "r"(a3), "r"(b0), "r"(b1))

__device__ __forceinline__ void bsplit(float v, unsigned short &h, unsigned short &l) {
    __nv_bfloat16 hb = __float2bfloat16_rn(v);
    __nv_bfloat16 lb = __float2bfloat16_rn(v - __bfloat162float(hb));
    h = __bfloat16_as_ushort(hb);
    l = __bfloat16_as_ushort(lb);
}
__device__ __forceinline__ uint32_t packbf(float lo, float hi) {
    __nv_bfloat162 b = __floats2bfloat162_rn(lo, hi);
    return *(uint32_t*)&b;
}
__device__ __forceinline__ unsigned short b16(float v) {
    return __bfloat16_as_ushort(__float2bfloat16_rn(v));
}

// ------------- RMSNorm -> plain bf16 xn -------------
__global__ __launch_bounds__(256)
void rmsnorm_bf16_kernel(const float* __restrict__ x, const float* __restrict__ w)
{
    const int row = blockIdx.x;
    const int tid = threadIdx.x;
    const float4* xr = (const float4*)(x + (size_t)row * DIM);
    float4 v0 = xr[tid];
    float4 v1 = xr[tid + 256];
    float s = v0.x*v0.x + v0.y*v0.y + v0.z*v0.z + v0.w*v0.w
            + v1.x*v1.x + v1.y*v1.y + v1.z*v1.z + v1.w*v1.w;
    #pragma unroll
    for (int o = 16; o > 0; o >>= 1) s += __shfl_xor_sync(0xffffffffu, s, o);
    __shared__ float red[8];
    if ((tid & 31) == 0) red[tid >> 5] = s;
    __syncthreads();
    float tot = red[0]+red[1]+red[2]+red[3]+red[4]+red[5]+red[6]+red[7];
    float r = rsqrtf(tot * (1.0f / (float)DIM) + 1e-6f);
    const float4* wr = (const float4*)w;
    float4 w0 = wr[tid], w1 = wr[tid + 256];
    unsigned short* ob = (unsigned short*)g_xnb + (size_t)row * DIM;
    *(ushort4*)(ob + tid * 4) =
        make_ushort4(b16(v0.x*r*w0.x), b16(v0.y*r*w0.y), b16(v0.z*r*w0.z), b16(v0.w*r*w0.w));
    *(ushort4*)(ob + (tid + 256) * 4) =
        make_ushort4(b16(v1.x*r*w1.x), b16(v1.y*r*w1.y), b16(v1.z*r*w1.z), b16(v1.w*r*w1.w));
}

// ------------- 3-term split conversion: [R,2048] fp32 -> [R,6144] bf16 -------------
// modeA=1: [hi|hi|lo]   modeA=0: [hi|lo|hi]
__global__ __launch_bounds__(256)
void convert_split_kernel(const float* __restrict__ in, __nv_bfloat16* __restrict__ out, int modeA)
{
    int idx = blockIdx.x * 256 + threadIdx.x;
    float4 v = ((const float4*)in)[idx];
    int r = idx >> 9, c = (idx & 511) * 4;
    unsigned short h[4], l[4];
    bsplit(v.x, h[0], l[0]); bsplit(v.y, h[1], l[1]);
    bsplit(v.z, h[2], l[2]); bsplit(v.w, h[3], l[3]);
    ushort4 hs = make_ushort4(h[0], h[1], h[2], h[3]);
    ushort4 ls = make_ushort4(l[0], l[1], l[2], l[3]);
    unsigned short* ob = (unsigned short*)out + (size_t)r * K3 + c;
    *(ushort4*)(ob)        = hs;
    *(ushort4*)(ob + 2048) = modeA ? hs : ls;
    *(ushort4*)(ob + 4096) = modeA ? ls : hs;
}

// ------------- weight plain bf16 conversion: fp32 [n,2048] -> bf16 [n,2048] -------------
__global__ __launch_bounds__(256)
void convert_wb_kernel(const float* __restrict__ w0, const float* __restrict__ w1,
                       const float* __restrict__ w2)
{
    const float* in = (blockIdx.y == 0) ? w0 : (blockIdx.y == 1) ? w1 : w2;
    unsigned short* out = (unsigned short*)(g_wb[0] + (size_t)blockIdx.y * DIM * DIM);
    int idx = blockIdx.x * 256 + threadIdx.x;
    float4 v = ((const float4*)in)[idx];
    *(ushort4*)(out + idx * 4) = make_ushort4(b16(v.x), b16(v.y), b16(v.z), b16(v.w));
}

// ================= HMMA bf16 GEMM =================
#define BM 128
#define BN 128
#define BK 64
#define GSTAGES 3
#define CHUNK_BYTES (BM*128 + BN*128)       // 32768
#define GEMM_SMEM (GSTAGES * CHUNK_BYTES + 1024)

// fp32-out version (3-term operands, KS = 6144):
template<int KS>
__global__ __launch_bounds__(256, 2)
void mma_gemm_kernel(const __nv_bfloat16* __restrict__ A,
                     const __nv_bfloat16* __restrict__ B,
                     float* __restrict__ C, int N)
{
    extern __shared__ char dynsm[];
    const uint32_t sb = (smem_u32(dynsm) + 1023u) & ~1023u;
    const int tid = threadIdx.x;
    const int w = tid >> 5, lane = tid & 31;
    const int wm = (w >> 2) * 64, wn = (w & 3) * 32;
    const int NCHUNK = KS / BK;

    const int mBase = blockIdx.y * BM;
    const int nBase = blockIdx.x * BN;
    const __nv_bfloat16* Ab = A + (size_t)mBase * KS;
    const __nv_bfloat16* Bb = B + (size_t)nBase * KS;

    float acc[4][4][4];
    #pragma unroll
    for (int i = 0; i < 4; i++)
        #pragma unroll
        for (int j = 0; j < 4; j++)
            #pragma unroll
            for (int q = 0; q < 4; q++) acc[i][j][q] = 0.f;

    auto load_chunk = [&](int c, int stage) {
        uint32_t abase = sb + stage * CHUNK_BYTES;
        uint32_t bbase = abase + BM * 128;
        #pragma unroll
        for (int t = 0; t < 8; t++) {
            int o = tid + t * 256;
            const __nv_bfloat16* src;
            uint32_t base;
            int row, c16;
            if (o < 1024) {
                row = o >> 3; c16 = o & 7;
                src = Ab + (size_t)row * KS + c * 64 + c16 * 8;
                base = abase;
            } else {
                int ob = o - 1024;
                row = ob >> 3; c16 = ob & 7;
                src = Bb + (size_t)row * KS + c * 64 + c16 * 8;
                base = bbase;
            }
            uint32_t off = (uint32_t)(row * 128 + c16 * 16);
            uint32_t dst = base + (off ^ ((off >> 3) & 0x70));
            asm volatile("cp.async.cg.shared.global [%0], [%1], 16;" :: "r"(dst), "l"(src) : "memory");
        }
        asm volatile("cp.async.commit_group;" ::: "memory");
    };

    load_chunk(0, 0);
    load_chunk(1, 1);

    const int rowadd = (lane & 7) + ((lane >> 3) & 1) * 8;
    const int colmi  = (lane >> 4) * 16;

    #pragma unroll 1
    for (int c = 0; c < NCHUNK; c++) {
        asm volatile("cp.async.wait_group %0;" :: "n"(1));
        __syncthreads();
        if (c + 2 < NCHUNK) load_chunk(c + 2, (c + 2) % GSTAGES);
        else asm volatile("cp.async.commit_group;" ::: "memory");

        uint32_t abase = sb + (c % GSTAGES) * CHUNK_BYTES;
        uint32_t bbase = abase + BM * 128;

        #pragma unroll
        for (int s = 0; s < 4; s++) {
            const int colb = s * 32 + colmi;
            uint32_t af[4][4];
            #pragma unroll
            for (int i = 0; i < 4; i++) {
                uint32_t off = (uint32_t)((wm + i * 16 + rowadd) * 128 + colb);
                LDSM_X4(af[i][0], af[i][1], af[i][2], af[i][3], abase + (off ^ ((off >> 3) & 0x70)));
            }
            uint32_t bf[2][4];
            #pragma unroll
            for (int j = 0; j < 2; j++) {
                uint32_t off = (uint32_t)((wn + j * 16 + rowadd) * 128 + colb);
                LDSM_X4(bf[j][0], bf[j][1], bf[j][2], bf[j][3], bbase + (off ^ ((off >> 3) & 0x70)));
            }
            #pragma unroll
            for (int i = 0; i < 4; i++)
                #pragma unroll
                for (int j = 0; j < 2; j++)
                    #pragma unroll
                    for (int ns = 0; ns < 2; ns++)
                        MMA_BF16(acc[i][j * 2 + ns],
                                 af[i][0], af[i][1], af[i][2], af[i][3],
                                 bf[j][ns], bf[j][2 + ns]);
        }
    }

    const int gid = lane >> 2, ctg = lane & 3;
    float* Cw = C + (size_t)(mBase + wm + gid) * N + nBase + wn + ctg * 2;
    #pragma unroll
    for (int i = 0; i < 4; i++)
        #pragma unroll
        for (int jn = 0; jn < 4; jn++) {
            float* p = Cw + (size_t)(i * 16) * N + jn * 8;
            *(float2*)p             = make_float2(acc[i][jn][0], acc[i][jn][1]);
            *(float2*)(p + 8 * N)   = make_float2(acc[i][jn][2], acc[i][jn][3]);
        }
}

// ---- merged QKV GEMM (K=2048 plain bf16, grid.z selects weight), bf16 row-major epilogue ----
__global__ __launch_bounds__(256, 2)
void mma_gemm_qkv_kernel()
{
    extern __shared__ char dynsm[];
    const uint32_t sb = (smem_u32(dynsm) + 1023u) & ~1023u;
    const int tid = threadIdx.x;
    const int w = tid >> 5, lane = tid & 31;
    const int wm = (w >> 2) * 64, wn = (w & 3) * 32;
    const int NCHUNK = DIM / BK;   // 32

    const int sel   = blockIdx.z;
    const int mBase = blockIdx.y * BM;
    const int nBase = blockIdx.x * BN;
    const __nv_bfloat16* Ab = g_xnb + (size_t)mBase * DIM;
    const __nv_bfloat16* Bb = g_wb[0] + (size_t)sel * DIM * DIM + (size_t)nBase * DIM;

    float acc[4][4][4];
    #pragma unroll
    for (int i = 0; i < 4; i++)
        #pragma unroll
        for (int j = 0; j < 4; j++)
            #pragma unroll
            for (int q = 0; q < 4; q++) acc[i][j][q] = 0.f;

    auto load_chunk = [&](int c, int stage) {
        uint32_t abase = sb + stage * CHUNK_BYTES;
        uint32_t bbase = abase + BM * 128;
        #pragma unroll
        for (int t = 0; t < 8; t++) {
            int o = tid + t * 256;
            const __nv_bfloat16* src;
            uint32_t base;
            int row, c16;
            if (o < 1024) {
                row = o >> 3; c16 = o & 7;
                src = Ab + (size_t)row * DIM + c * 64 + c16 * 8;
                base = abase;
            } else {
                int ob = o - 1024;
                row = ob >> 3; c16 = ob & 7;
                src = Bb + (size_t)row * DIM + c * 64 + c16 * 8;
                base = bbase;
            }
            uint32_t off = (uint32_t)(row * 128 + c16 * 16);
            uint32_t dst = base + (off ^ ((off >> 3) & 0x70));
            asm volatile("cp.async.cg.shared.global [%0], [%1], 16;" :: "r"(dst), "l"(src) : "memory");
        }
        asm volatile("cp.async.commit_group;" ::: "memory");
    };

    load_chunk(0, 0);
    load_chunk(1, 1);

    const int rowadd = (lane & 7) + ((lane >> 3) & 1) * 8;
    const int colmi  = (lane >> 4) * 16;

    #pragma unroll 1
    for (int c = 0; c < NCHUNK; c++) {
        asm volatile("cp.async.wait_group %0;" :: "n"(1));
        __syncthreads();
        if (c + 2 < NCHUNK) load_chunk(c + 2, (c + 2) % GSTAGES);
        else asm volatile("cp.async.commit_group;" ::: "memory");

        uint32_t abase = sb + (c % GSTAGES) * CHUNK_BYTES;
        uint32_t bbase = abase + BM * 128;

        #pragma unroll
        for (int s = 0; s < 4; s++) {
            const int colb = s * 32 + colmi;
            uint32_t af[4][4];
            #pragma unroll
            for (int i = 0; i < 4; i++) {
                uint32_t off = (uint32_t)((wm + i * 16 + rowadd) * 128 + colb);
                LDSM_X4(af[i][0], af[i][1], af[i][2], af[i][3], abase + (off ^ ((off >> 3) & 0x70)));
            }
            uint32_t bf[2][4];
            #pragma unroll
            for (int j = 0; j < 2; j++) {
                uint32_t off = (uint32_t)((wn + j * 16 + rowadd) * 128 + colb);
                LDSM_X4(bf[j][0], bf[j][1], bf[j][2], bf[j][3], bbase + (off ^ ((off >> 3) & 0x70)));
            }
            #pragma unroll
            for (int i = 0; i < 4; i++)
                #pragma unroll
                for (int j = 0; j < 2; j++)
                    #pragma unroll
                    for (int ns = 0; ns < 2; ns++)
                        MMA_BF16(acc[i][j * 2 + ns],
                                 af[i][0], af[i][1], af[i][2], af[i][3],
                                 bf[j][ns], bf[j][2 + ns]);
        }
    }

    // bf16 row-major epilogue into [b,t,h*d]
    unsigned short* outp = (unsigned short*)(sel == 0 ? g_qb : sel == 1 ? g_kb : g_vb);
    const int gid = lane >> 2, ctg = lane & 3;
    unsigned short* Cw = outp + (size_t)(mBase + wm + gid) * DIM + nBase + wn + ctg * 2;
    #pragma unroll
    for (int i = 0; i < 4; i++)
        #pragma unroll
        for (int jn = 0; jn < 4; jn++) {
            unsigned short* p = Cw + (size_t)(i * 16) * DIM + jn * 8;
            *(ushort2*)p               = make_ushort2(b16(acc[i][jn][0]), b16(acc[i][jn][1]));
            *(ushort2*)(p + 8 * DIM)   = make_ushort2(b16(acc[i][jn][2]), b16(acc[i][jn][3]));
        }
}

// ------------- HMMA causal softcapped flash attention (BQ=128, BK=64) -------------
// reads bf16 [b,t,h*d] (row stride DIM, head offset h*HD)
#define AST 136
#define KV_BYTES (2 * 64 * AST * 2)
#define ATT2_SMEM (128 * AST * 2 + 2 * KV_BYTES)

__global__ __launch_bounds__(256)
void attn_mma_kernel(const __nv_bfloat16* __restrict__ Qg,
                     const __nv_bfloat16* __restrict__ Kg,
                     const __nv_bfloat16* __restrict__ Vg)
{
    extern __shared__ char smraw[];
    const uint32_t sQ  = smem_u32(smraw);
    const uint32_t sKV = sQ + 128 * AST * 2;

    const int tid = threadIdx.x;
    const int w = tid >> 5, lane = tid & 31;
    const int qt = (int)gridDim.x - 1 - (int)blockIdx.x;
    const int h  = blockIdx.y;
    const int b  = blockIdx.z;

    const __nv_bfloat16* Qb = Qg + (size_t)(b * TT + qt * 128) * DIM + h * HD;
    const __nv_bfloat16* Kb = Kg + (size_t)(b * TT) * DIM + h * HD;
    const __nv_bfloat16* Vb = Vg + (size_t)(b * TT) * DIM + h * HD;

    #pragma unroll
    for (int t = 0; t < 8; t++) {
        int ch = tid + t * 256;
        int row = ch >> 4, c16 = ch & 15;
        uint32_t dst = sQ + row * 272 + c16 * 16;
        const __nv_bfloat16* src = Qb + (size_t)row * DIM + c16 * 8;
        asm volatile("cp.async.cg.shared.global [%0], [%1], 16;" :: "r"(dst), "l"(src) : "memory");
    }
    asm volatile("cp.async.commit_group;" ::: "memory");

    auto loadKV = [&](int kt, int stage) {
        uint32_t base = sKV + stage * KV_BYTES;
        const __nv_bfloat16* Kt = Kb + (size_t)kt * 64 * DIM;
        const __nv_bfloat16* Vt = Vb + (size_t)kt * 64 * DIM;
        #pragma unroll
        for (int t = 0; t < 8; t++) {
            int ch = tid + t * 256;
            int row = (ch >> 4) & 63, c16 = ch & 15;
            bool isV = ch >= 1024;
            const __nv_bfloat16* src = (isV ? Vt : Kt) + (size_t)row * DIM + c16 * 8;
            uint32_t dst = base + (isV ? (64u * 272u) : 0u) + row * 272 + c16 * 16;
            asm volatile("cp.async.cg.shared.global [%0], [%1], 16;" :: "r"(dst), "l"(src) : "memory");
        }
        asm volatile("cp.async.commit_group;" ::: "memory");
    };

    const int numK = 2 * qt + 2;
    loadKV(0, 0);
    loadKV(1, 1);

    float oacc[16][4];
    #pragma unroll
    for (int j = 0; j < 16; j++)
        #pragma unroll
        for (int q = 0; q < 4; q++) oacc[j][q] = 0.f;
    float den0 = 0.f, den1 = 0.f;

    const int rowadd = (lane & 7) + ((lane >> 3) & 1) * 8;
    const int colmi  = (lane >> 4) * 16;
    const int colq   = (lane & 3) * 2;
    const int rr0    = qt * 128 + w * 16 + (lane >> 2);

    #pragma unroll 1
    for (int kt = 0; kt < numK; kt++) {
        asm volatile("cp.async.wait_group %0;" :: "n"(1));
        __syncthreads();
        const uint32_t sK = sKV + (kt & 1) * KV_BYTES;
        const uint32_t sV = sK + 64u * 272u;

        float cs[8][4];
        #pragma unroll
        for (int j = 0; j < 8; j++)
            #pragma unroll
            for (int q = 0; q < 4; q++) cs[j][q] = 0.f;

        #pragma unroll
        for (int s = 0; s < 8; s++) {
            uint32_t a0, a1, a2, a3;
            LDSM_X4(a0, a1, a2, a3, sQ + (w * 16 + rowadd) * 272 + s * 32 + colmi);
            #pragma unroll
            for (int g = 0; g < 4; g++) {
                uint32_t k0, k1, k2, k3;
                LDSM_X4(k0, k1, k2, k3, sK + (g * 16 + rowadd) * 272 + s * 32 + colmi);
                MMA_BF16(cs[2*g],   a0, a1, a2, a3, k0, k2);
                MMA_BF16(cs[2*g+1], a0, a1, a2, a3, k1, k3);
            }
        }

        const bool msk = (kt >= 2 * qt);
        #pragma unroll
        for (int j = 0; j < 8; j++) {
            const int cb = kt * 64 + j * 8 + colq;
            #pragma unroll
            for (int q = 0; q < 4; q++) {
                float sv = cs[j][q] * SCALE_QK;
                float xx = sv * (1.0f / SOFTCAP);
                float x2 = xx * xx;
                float capped;
                if (fabsf(xx) > 0.55f) capped = SOFTCAP * tanhf(xx);
                else capped = sv * (1.0f - x2 * (0.33333334f - x2 * (0.13333334f - x2 * 0.05396825f)));
                float p = __expf(capped);
                if (msk) {
                    int col = cb + (q & 1);
                    int rowg = rr0 + (q >> 1) * 8;
                    if (col > rowg) p = 0.f;
                }
                cs[j][q] = p;
                if (q >> 1) den1 += p; else den0 += p;
            }
        }

        uint32_t pa[4][4];
        #pragma unroll
        for (int kk = 0; kk < 4; kk++) {
            pa[kk][0] = packbf(cs[2*kk][0],   cs[2*kk][1]);
            pa[kk][1] = packbf(cs[2*kk][2],   cs[2*kk][3]);
            pa[kk][2] = packbf(cs[2*kk+1][0], cs[2*kk+1][1]);
            pa[kk][3] = packbf(cs[2*kk+1][2], cs[2*kk+1][3]);
        }

        #pragma unroll
        for (int kk = 0; kk < 4; kk++) {
            #pragma unroll
            for (int g = 0; g < 8; g++) {
                uint32_t v0, v1, v2, v3;
                LDSM_X4_T(v0, v1, v2, v3, sV + (kk * 16 + rowadd) * 272 + g * 32 + colmi);
                MMA_BF16(oacc[2*g],   pa[kk][0], pa[kk][1], pa[kk][2], pa[kk][3], v0, v1);
                MMA_BF16(oacc[2*g+1], pa[kk][0], pa[kk][1], pa[kk][2], pa[kk][3], v2, v3);
            }
        }

        __syncthreads();
        if (kt + 2 < numK) loadKV(kt + 2, kt & 1);
        else asm volatile("cp.async.commit_group;" ::: "memory");
    }

    den0 += __shfl_xor_sync(0xffffffffu, den0, 1);
    den0 += __shfl_xor_sync(0xffffffffu, den0, 2);
    den1 += __shfl_xor_sync(0xffffffffu, den1, 1);
    den1 += __shfl_xor_sync(0xffffffffu, den1, 2);
    const float i0 = 1.0f / den0, i1 = 1.0f / den1;

    const int t0 = qt * 128 + w * 16 + (lane >> 2);
    unsigned short* outb = (unsigned short*)g_at3;
    size_t base0 = ((size_t)(b * TT + t0)) * K3 + h * 128 + colq;
    size_t base1 = base0 + (size_t)8 * K3;
    #pragma unroll
    for (int j = 0; j < 16; j++) {
        float p0 = oacc[j][0] * i0, p1 = oacc[j][1] * i0;
        float p2 = oacc[j][2] * i1, p3 = oacc[j][3] * i1;
        unsigned short h0, l0, h1, l1, h2, l2, h3, l3;
        bsplit(p0, h0, l0); bsplit(p1, h1, l1);
        bsplit(p2, h2, l2); bsplit(p3, h3, l3);
        unsigned short* q0 = outb + base0 + j * 8;
        unsigned short* q1 = outb + base1 + j * 8;
        *(ushort2*)(q0)        = make_ushort2(h0, h1);
        *(ushort2*)(q0 + 2048) = make_ushort2(h0, h1);
        *(ushort2*)(q0 + 4096) = make_ushort2(l0, l1);
        *(ushort2*)(q1)        = make_ushort2(h2, h3);
        *(ushort2*)(q1 + 2048) = make_ushort2(h2, h3);
        *(ushort2*)(q1 + 4096) = make_ushort2(l2, l3);
    }
}

// ---------------------------- gate + residual blend ---------------------------
__global__ __launch_bounds__(256)
void blend_kernel(const float* __restrict__ x, const float* __restrict__ gb,
                  float* __restrict__ out)
{
    const int i4 = blockIdx.x * 256 + threadIdx.x;
    const int col4 = i4 & 511;
    float4 xv = ((const float4*)x)[i4];
    float4 ov = ((const float4*)g_op)[i4];
    float4 gv = ((const float4*)g_gl)[i4];
    float4 bv = ((const float4*)gb)[col4];
    float a0 = 1.0f / (1.0f + __expf(-(gv.x + bv.x)));
    float a1 = 1.0f / (1.0f + __expf(-(gv.y + bv.y)));
    float a2 = 1.0f / (1.0f + __expf(-(gv.z + bv.z)));
    float a3 = 1.0f / (1.0f + __expf(-(gv.w + bv.w)));
    float4 r;
    r.x = xv.x + a0 * (ov.x - xv.x);
    r.y = xv.y + a1 * (ov.y - xv.y);
    r.z = xv.z + a2 * (ov.z - xv.z);
    r.w = xv.w + a3 * (ov.w - xv.w);
    ((float4*)out)[i4] = r;
}

// ----------------------------------- launch -----------------------------------
extern "C" void kernel_launch(void* const* d_in, const int* in_sizes, int n_in,
                              void* d_out, int out_size)
{
    (void)in_sizes; (void)n_in; (void)out_size;
    const float* x   = (const float*)d_in[0];
    const float* Wq  = (const float*)d_in[2];
    const float* Wk  = (const float*)d_in[3];
    const float* Wv  = (const float*)d_in[4];
    const float* Wo  = (const float*)d_in[5];
    const float* lnw = (const float*)d_in[6];
    const float* gW  = (const float*)d_in[7];
    const float* gb  = (const float*)d_in[8];
    float* out = (float*)d_out;

    static int attr_set = 0;
    static cudaStream_t s1 = nullptr;
    static cudaEvent_t evFork = nullptr, evJoin = nullptr, evQKV = nullptr, evConv = nullptr;
    if (!attr_set) {
        cudaFuncSetAttribute(mma_gemm_kernel<K3>, cudaFuncAttributeMaxDynamicSharedMemorySize, GEMM_SMEM);
        cudaFuncSetAttribute(mma_gemm_qkv_kernel, cudaFuncAttributeMaxDynamicSharedMemorySize, GEMM_SMEM);
        cudaFuncSetAttribute(attn_mma_kernel,     cudaFuncAttributeMaxDynamicSharedMemorySize, ATT2_SMEM);
        cudaStreamCreateWithFlags(&s1, cudaStreamNonBlocking);
        cudaEventCreateWithFlags(&evFork, cudaEventDisableTiming);
        cudaEventCreateWithFlags(&evJoin, cudaEventDisableTiming);
        cudaEventCreateWithFlags(&evQKV, cudaEventDisableTiming);
        cudaEventCreateWithFlags(&evConv, cudaEventDisableTiming);
        attr_set = 1;
    }

    void *pop, *pgl, *px3, *pat3, *pw3, *pqb, *pkb, *pvb;
    cudaGetSymbolAddress(&pop, g_op);
    cudaGetSymbolAddress(&pgl, g_gl);
    cudaGetSymbolAddress(&px3,  g_x3);
    cudaGetSymbolAddress(&pat3, g_at3);
    cudaGetSymbolAddress(&pw3,  g_w3);
    cudaGetSymbolAddress(&pqb, g_qb);
    cudaGetSymbolAddress(&pkb, g_kb);
    cudaGetSymbolAddress(&pvb, g_vb);
    __nv_bfloat16* w3 = (__nv_bfloat16*)pw3;
    const size_t WSTRIDE3 = (size_t)DIM * K3;

    dim3 gGemm(DIM / BN, MTOT / BM);        // (16, 32)

    // ---- fork side stream: small conversions only (x3, gW, Wo) ----
    cudaEventRecord(evFork, 0);
    cudaStreamWaitEvent(s1, evFork, 0);

    convert_split_kernel<<<(MTOT * (DIM/4)) / 256, 256, 0, s1>>>(x, (__nv_bfloat16*)px3, 1);
    convert_split_kernel<<<(DIM  * (DIM/4)) / 256, 256, 0, s1>>>(gW, w3 + 1 * WSTRIDE3, 0);
    convert_split_kernel<<<(DIM  * (DIM/4)) / 256, 256, 0, s1>>>(Wo, w3 + 0 * WSTRIDE3, 0);
    cudaEventRecord(evConv, s1);

    // ---- main stream: rmsnorm -> wb convert -> QKV GEMM (uncontended) ----
    rmsnorm_bf16_kernel<<<MTOT, 256>>>(x, lnw);
    dim3 gWb((DIM * (DIM/4)) / 256, 3);
    convert_wb_kernel<<<gWb, 256>>>(Wq, Wk, Wv);

    dim3 gQKV(DIM / BN, MTOT / BM, 3);      // (16, 32, 3)
    mma_gemm_qkv_kernel<<<gQKV, 256, GEMM_SMEM>>>();
    cudaEventRecord(evQKV, 0);

    // ---- s1: gate GEMM overlapping attention + Wo (low-tensor windows) ----
    cudaStreamWaitEvent(s1, evQKV, 0);
    mma_gemm_kernel<K3><<<gGemm, 256, GEMM_SMEM, s1>>>((const __nv_bfloat16*)px3, w3 + 1 * WSTRIDE3, (float*)pgl, DIM);
    cudaEventRecord(evJoin, s1);

    // ---- main stream: attention -> Wo GEMM ----
    dim3 gAttn(TT / 128, NH, BB);           // (16, 16, 2)
    attn_mma_kernel<<<gAttn, 256, ATT2_SMEM>>>((const __nv_bfloat16*)pqb,
                                               (const __nv_bfloat16*)pkb,
                                               (const __nv_bfloat16*)pvb);

    cudaStreamWaitEvent(0, evConv, 0);      // Wo weights ready (long since)
    mma_gemm_kernel<K3><<<gGemm, 256, GEMM_SMEM>>>((const __nv_bfloat16*)pat3, w3 + 0 * WSTRIDE3, (float*)pop, DIM);

    // gate result needed only by blend
    cudaStreamWaitEvent(0, evJoin, 0);
    blend_kernel<<<(MTOT * DIM / 4) / 256, 256>>>(x, gb, out);
}

// round 16
// speedup vs baseline: 1.6702x; 1.0368x over previous
#include <cuda_runtime.h>
#include <cuda_bf16.h>
#include <math.h>
#include <stdint.h>

#define BB   2
#define TT   2048
#define DIM  2048
#define NH   16
#define HD   128
#define MTOT (BB*TT)
#define K3   6144
#define K2   4096
#define SCALE_QK 0.08838834764831843f
#define SOFTCAP 30.0f

// ---------------- scratch ----------------
__device__ float g_op[MTOT * DIM];
__device__ float g_gl[MTOT * DIM];
__device__ __nv_bfloat16 g_xnb[(size_t)MTOT * DIM];     // plain bf16 xn
__device__ __nv_bfloat16 g_x2 [(size_t)MTOT * K2];      // x  [hi|lo]
__device__ __nv_bfloat16 g_at2[(size_t)MTOT * K2];      // at [hi|lo]
__device__ __nv_bfloat16 g_w3[2][(size_t)DIM * K3];     // Wo, gW  [hi|lo|hi]
__device__ __nv_bfloat16 g_wb[3][(size_t)DIM * DIM];    // Wq,Wk,Wv plain bf16
__device__ __nv_bfloat16 g_qb[(size_t)MTOT * DIM];      // [b,t,h*d] bf16
__device__ __nv_bfloat16 g_kb[(size_t)MTOT * DIM];
__device__ __nv_bfloat16 g_vb[(size_t)MTOT * DIM];

// ---------------- helpers ----------------
__device__ __forceinline__ uint32_t smem_u32(const void* p) {
    uint32_t a;
    asm("{ .reg .u64 t; cvta.to.shared.u64 t, %1; cvt.u32.u64 %0, t; }" : "=r"(a) : "l"(p));
    return a;
}

#define LDSM_X4(r0, r1, r2, r3, a) \
    asm volatile("ldmatrix.sync.aligned.m8n8.x4.shared.b16 {%0,%1,%2,%3}, [%4];" \
        : "=r"(r0), "=r"(r1), "=r"(r2), "=r"(r3) : "r"(a))
#define LDSM_X4_T(r0, r1, r2, r3, a) \
    asm volatile("ldmatrix.sync.aligned.m8n8.x4.trans.shared.b16 {%0,%1,%2,%3}, [%4];" \
        : "=r"(r0), "=r"(r1), "=r"(r2), "=r"(r3) : "r"(a))
#define MMA_BF16(c, a0, a1, a2, a3, b0, b1) \
    asm volatile("mma.sync.aligned.m16n8k16.row.col.f32.bf16.bf16.f32 " \
        "{%0,%1,%2,%3}, {%4,%5,%6,%7}, {%8,%9}, {%0,%1,%2,%3};" \
        : "+f"((c)[0]), "+f"((c)[1]), "+f"((c)[2]), "+f"((c)[3]) \
        : "r"(a0), "r"(a1), "r"(a2), "r"(a3), "r"(b0), "r"(b1))

__device__ __forceinline__ void bsplit(float v, unsigned short &h, unsigned short &l) {
    __nv_bfloat16 hb = __float2bfloat16_rn(v);
    __nv_bfloat16 lb = __float2bfloat16_rn(v - __bfloat162float(hb));
    h = __bfloat16_as_ushort(hb);
    l = __bfloat16_as_ushort(lb);
}
__device__ __forceinline__ uint32_t packbf(float lo, float hi) {
    __nv_bfloat162 b = __floats2bfloat162_rn(lo, hi);
    return *(uint32_t*)&b;
}
__device__ __forceinline__ unsigned short b16(float v) {
    return __bfloat16_as_ushort(__float2bfloat16_rn(v));
}

// ------------- RMSNorm -> plain bf16 xn -------------
__global__ __launch_bounds__(256)
void rmsnorm_bf16_kernel(const float* __restrict__ x, const float* __restrict__ w)
{
    const int row = blockIdx.x;
    const int tid = threadIdx.x;
    const float4* xr = (const float4*)(x + (size_t)row * DIM);
    float4 v0 = xr[tid];
    float4 v1 = xr[tid + 256];
    float s = v0.x*v0.x + v0.y*v0.y + v0.z*v0.z + v0.w*v0.w
            + v1.x*v1.x + v1.y*v1.y + v1.z*v1.z + v1.w*v1.w;
    #pragma unroll
    for (int o = 16; o > 0; o >>= 1) s += __shfl_xor_sync(0xffffffffu, s, o);
    __shared__ float red[8];
    if ((tid & 31) == 0) red[tid >> 5] = s;
    __syncthreads();
    float tot = red[0]+red[1]+red[2]+red[3]+red[4]+red[5]+red[6]+red[7];
    float r = rsqrtf(tot * (1.0f / (float)DIM) + 1e-6f);
    const float4* wr = (const float4*)w;
    float4 w0 = wr[tid], w1 = wr[tid + 256];
    unsigned short* ob = (unsigned short*)g_xnb + (size_t)row * DIM;
    *(ushort4*)(ob + tid * 4) =
        make_ushort4(b16(v0.x*r*w0.x), b16(v0.y*r*w0.y), b16(v0.z*r*w0.z), b16(v0.w*r*w0.w));
    *(ushort4*)(ob + (tid + 256) * 4) =
        make_ushort4(b16(v1.x*r*w1.x), b16(v1.y*r*w1.y), b16(v1.z*r*w1.z), b16(v1.w*r*w1.w));
}

// ------------- 2-term split conversion: [R,2048] fp32 -> [R,4096] bf16 [hi|lo] -------------
__global__ __launch_bounds__(256)
void convert_split2_kernel(const float* __restrict__ in, __nv_bfloat16* __restrict__ out)
{
    int idx = blockIdx.x * 256 + threadIdx.x;
    float4 v = ((const float4*)in)[idx];
    int r = idx >> 9, c = (idx & 511) * 4;
    unsigned short h[4], l[4];
    bsplit(v.x, h[0], l[0]); bsplit(v.y, h[1], l[1]);
    bsplit(v.z, h[2], l[2]); bsplit(v.w, h[3], l[3]);
    unsigned short* ob = (unsigned short*)out + (size_t)r * K2 + c;
    *(ushort4*)(ob)        = make_ushort4(h[0], h[1], h[2], h[3]);
    *(ushort4*)(ob + 2048) = make_ushort4(l[0], l[1], l[2], l[3]);
}

// ------------- 3-term weight conversion: fp32 [n,2048] -> bf16 [n,6144] [hi|lo|hi] -------------
__global__ __launch_bounds__(256)
void convert_split3_kernel(const float* __restrict__ in, __nv_bfloat16* __restrict__ out)
{
    int idx = blockIdx.x * 256 + threadIdx.x;
    float4 v = ((const float4*)in)[idx];
    int r = idx >> 9, c = (idx & 511) * 4;
    unsigned short h[4], l[4];
    bsplit(v.x, h[0], l[0]); bsplit(v.y, h[1], l[1]);
    bsplit(v.z, h[2], l[2]); bsplit(v.w, h[3], l[3]);
    ushort4 hs = make_ushort4(h[0], h[1], h[2], h[3]);
    ushort4 ls = make_ushort4(l[0], l[1], l[2], l[3]);
    unsigned short* ob = (unsigned short*)out + (size_t)r * K3 + c;
    *(ushort4*)(ob)        = hs;
    *(ushort4*)(ob + 2048) = ls;
    *(ushort4*)(ob + 4096) = hs;
}

// ------------- weight plain bf16 conversion -------------
__global__ __launch_bounds__(256)
void convert_wb_kernel(const float* __restrict__ w0, const float* __restrict__ w1,
                       const float* __restrict__ w2)
{
    const float* in = (blockIdx.y == 0) ? w0 : (blockIdx.y == 1) ? w1 : w2;
    unsigned short* out = (unsigned short*)(g_wb[0] + (size_t)blockIdx.y * DIM * DIM);
    int idx = blockIdx.x * 256 + threadIdx.x;
    float4 v = ((const float4*)in)[idx];
    *(ushort4*)(out + idx * 4) = make_ushort4(b16(v.x), b16(v.y), b16(v.z), b16(v.w));
}

// ================= HMMA bf16 GEMM =================
#define BM 128
#define BN 128
#define BK 64
#define GSTAGES 3
#define CHUNK_BYTES (BM*128 + BN*128)       // 32768
#define GEMM_SMEM (GSTAGES * CHUNK_BYTES + 1024)

// ---- 3-term GEMM with 2-term A storage:
// logical K = 6144 (96 chunks); A physical [hi|lo] K2=4096, chunk remap c<32?c:c-32
// B physical [hi|lo|hi] K3=6144, direct.
__global__ __launch_bounds__(256, 2)
void mma_gemm3_kernel(const __nv_bfloat16* __restrict__ A,
                      const __nv_bfloat16* __restrict__ B,
                      float* __restrict__ C, int N)
{
    extern __shared__ char dynsm[];
    const uint32_t sb = (smem_u32(dynsm) + 1023u) & ~1023u;
    const int tid = threadIdx.x;
    const int w = tid >> 5, lane = tid & 31;
    const int wm = (w >> 2) * 64, wn = (w & 3) * 32;
    const int NCHUNK = K3 / BK;   // 96 logical

    const int mBase = blockIdx.y * BM;
    const int nBase = blockIdx.x * BN;
    const __nv_bfloat16* Ab = A + (size_t)mBase * K2;
    const __nv_bfloat16* Bb = B + (size_t)nBase * K3;

    float acc[4][4][4];
    #pragma unroll
    for (int i = 0; i < 4; i++)
        #pragma unroll
        for (int j = 0; j < 4; j++)
            #pragma unroll
            for (int q = 0; q < 4; q++) acc[i][j][q] = 0.f;

    auto load_chunk = [&](int c, int stage) {
        const int ca = (c < 32) ? c : (c - 32);   // A chunk remap (hi reused)
        uint32_t abase = sb + stage * CHUNK_BYTES;
        uint32_t bbase = abase + BM * 128;
        #pragma unroll
        for (int t = 0; t < 8; t++) {
            int o = tid + t * 256;
            const __nv_bfloat16* src;
            uint32_t base;
            int row, c16;
            if (o < 1024) {
                row = o >> 3; c16 = o & 7;
                src = Ab + (size_t)row * K2 + ca * 64 + c16 * 8;
                base = abase;
            } else {
                int ob = o - 1024;
                row = ob >> 3; c16 = ob & 7;
                src = Bb + (size_t)row * K3 + c * 64 + c16 * 8;
                base = bbase;
            }
            uint32_t off = (uint32_t)(row * 128 + c16 * 16);
            uint32_t dst = base + (off ^ ((off >> 3) & 0x70));
            asm volatile("cp.async.cg.shared.global [%0], [%1], 16;" :: "r"(dst), "l"(src) : "memory");
        }
        asm volatile("cp.async.commit_group;" ::: "memory");
    };

    load_chunk(0, 0);
    load_chunk(1, 1);

    const int rowadd = (lane & 7) + ((lane >> 3) & 1) * 8;
    const int colmi  = (lane >> 4) * 16;

    #pragma unroll 1
    for (int c = 0; c < NCHUNK; c++) {
        asm volatile("cp.async.wait_group %0;" :: "n"(1));
        __syncthreads();
        if (c + 2 < NCHUNK) load_chunk(c + 2, (c + 2) % GSTAGES);
        else asm volatile("cp.async.commit_group;" ::: "memory");

        uint32_t abase = sb + (c % GSTAGES) * CHUNK_BYTES;
        uint32_t bbase = abase + BM * 128;

        #pragma unroll
        for (int s = 0; s < 4; s++) {
            const int colb = s * 32 + colmi;
            uint32_t af[4][4];
            #pragma unroll
            for (int i = 0; i < 4; i++) {
                uint32_t off = (uint32_t)((wm + i * 16 + rowadd) * 128 + colb);
                LDSM_X4(af[i][0], af[i][1], af[i][2], af[i][3], abase + (off ^ ((off >> 3) & 0x70)));
            }
            uint32_t bf[2][4];
            #pragma unroll
            for (int j = 0; j < 2; j++) {
                uint32_t off = (uint32_t)((wn + j * 16 + rowadd) * 128 + colb);
                LDSM_X4(bf[j][0], bf[j][1], bf[j][2], bf[j][3], bbase + (off ^ ((off >> 3) & 0x70)));
            }
            #pragma unroll
            for (int i = 0; i < 4; i++)
                #pragma unroll
                for (int j = 0; j < 2; j++)
                    #pragma unroll
                    for (int ns = 0; ns < 2; ns++)
                        MMA_BF16(acc[i][j * 2 + ns],
                                 af[i][0], af[i][1], af[i][2], af[i][3],
                                 bf[j][ns], bf[j][2 + ns]);
        }
    }

    const int gid = lane >> 2, ctg = lane & 3;
    float* Cw = C + (size_t)(mBase + wm + gid) * N + nBase + wn + ctg * 2;
    #pragma unroll
    for (int i = 0; i < 4; i++)
        #pragma unroll
        for (int jn = 0; jn < 4; jn++) {
            float* p = Cw + (size_t)(i * 16) * N + jn * 8;
            *(float2*)p             = make_float2(acc[i][jn][0], acc[i][jn][1]);
            *(float2*)(p + 8 * N)   = make_float2(acc[i][jn][2], acc[i][jn][3]);
        }
}

// ---- merged QKV GEMM (K=2048 plain bf16, grid.z selects weight), bf16 row-major epilogue ----
__global__ __launch_bounds__(256, 2)
void mma_gemm_qkv_kernel()
{
    extern __shared__ char dynsm[];
    const uint32_t sb = (smem_u32(dynsm) + 1023u) & ~1023u;
    const int tid = threadIdx.x;
    const int w = tid >> 5, lane = tid & 31;
    const int wm = (w >> 2) * 64, wn = (w & 3) * 32;
    const int NCHUNK = DIM / BK;   // 32

    const int sel   = blockIdx.z;
    const int mBase = blockIdx.y * BM;
    const int nBase = blockIdx.x * BN;
    const __nv_bfloat16* Ab = g_xnb + (size_t)mBase * DIM;
    const __nv_bfloat16* Bb = g_wb[0] + (size_t)sel * DIM * DIM + (size_t)nBase * DIM;

    float acc[4][4][4];
    #pragma unroll
    for (int i = 0; i < 4; i++)
        #pragma unroll
        for (int j = 0; j < 4; j++)
            #pragma unroll
            for (int q = 0; q < 4; q++) acc[i][j][q] = 0.f;

    auto load_chunk = [&](int c, int stage) {
        uint32_t abase = sb + stage * CHUNK_BYTES;
        uint32_t bbase = abase + BM * 128;
        #pragma unroll
        for (int t = 0; t < 8; t++) {
            int o = tid + t * 256;
            const __nv_bfloat16* src;
            uint32_t base;
            int row, c16;
            if (o < 1024) {
                row = o >> 3; c16 = o & 7;
                src = Ab + (size_t)row * DIM + c * 64 + c16 * 8;
                base = abase;
            } else {
                int ob = o - 1024;
                row = ob >> 3; c16 = ob & 7;
                src = Bb + (size_t)row * DIM + c * 64 + c16 * 8;
                base = bbase;
            }
            uint32_t off = (uint32_t)(row * 128 + c16 * 16);
            uint32_t dst = base + (off ^ ((off >> 3) & 0x70));
            asm volatile("cp.async.cg.shared.global [%0], [%1], 16;" :: "r"(dst), "l"(src) : "memory");
        }
        asm volatile("cp.async.commit_group;" ::: "memory");
    };

    load_chunk(0, 0);
    load_chunk(1, 1);

    const int rowadd = (lane & 7) + ((lane >> 3) & 1) * 8;
    const int colmi  = (lane >> 4) * 16;

    #pragma unroll 1
    for (int c = 0; c < NCHUNK; c++) {
        asm volatile("cp.async.wait_group %0;" :: "n"(1));
        __syncthreads();
        if (c + 2 < NCHUNK) load_chunk(c + 2, (c + 2) % GSTAGES);
        else asm volatile("cp.async.commit_group;" ::: "memory");

        uint32_t abase = sb + (c % GSTAGES) * CHUNK_BYTES;
        uint32_t bbase = abase + BM * 128;

        #pragma unroll
        for (int s = 0; s < 4; s++) {
            const int colb = s * 32 + colmi;
            uint32_t af[4][4];
            #pragma unroll
            for (int i = 0; i < 4; i++) {
                uint32_t off = (uint32_t)((wm + i * 16 + rowadd) * 128 + colb);
                LDSM_X4(af[i][0], af[i][1], af[i][2], af[i][3], abase + (off ^ ((off >> 3) & 0x70)));
            }
            uint32_t bf[2][4];
            #pragma unroll
            for (int j = 0; j < 2; j++) {
                uint32_t off = (uint32_t)((wn + j * 16 + rowadd) * 128 + colb);
                LDSM_X4(bf[j][0], bf[j][1], bf[j][2], bf[j][3], bbase + (off ^ ((off >> 3) & 0x70)));
            }
            #pragma unroll
            for (int i = 0; i < 4; i++)
                #pragma unroll
                for (int j = 0; j < 2; j++)
                    #pragma unroll
                    for (int ns = 0; ns < 2; ns++)
                        MMA_BF16(acc[i][j * 2 + ns],
                                 af[i][0], af[i][1], af[i][2], af[i][3],
                                 bf[j][ns], bf[j][2 + ns]);
        }
    }

    unsigned short* outp = (unsigned short*)(sel == 0 ? g_qb : sel == 1 ? g_kb : g_vb);
    const int gid = lane >> 2, ctg = lane & 3;
    unsigned short* Cw = outp + (size_t)(mBase + wm + gid) * DIM + nBase + wn + ctg * 2;
    #pragma unroll
    for (int i = 0; i < 4; i++)
        #pragma unroll
        for (int jn = 0; jn < 4; jn++) {
            unsigned short* p = Cw + (size_t)(i * 16) * DIM + jn * 8;
            *(ushort2*)p               = make_ushort2(b16(acc[i][jn][0]), b16(acc[i][jn][1]));
            *(ushort2*)(p + 8 * DIM)   = make_ushort2(b16(acc[i][jn][2]), b16(acc[i][jn][3]));
        }
}

// ------------- HMMA causal softcapped flash attention (BQ=128, BK=64) -------------
#define AST 136
#define KV_BYTES (2 * 64 * AST * 2)
#define ATT2_SMEM (128 * AST * 2 + 2 * KV_BYTES)

__global__ __launch_bounds__(256)
void attn_mma_kernel(const __nv_bfloat16* __restrict__ Qg,
                     const __nv_bfloat16* __restrict__ Kg,
                     const __nv_bfloat16* __restrict__ Vg)
{
    extern __shared__ char smraw[];
    const uint32_t sQ  = smem_u32(smraw);
    const uint32_t sKV = sQ + 128 * AST * 2;

    const int tid = threadIdx.x;
    const int w = tid >> 5, lane = tid & 31;
    const int qt = (int)gridDim.x - 1 - (int)blockIdx.x;
    const int h  = blockIdx.y;
    const int b  = blockIdx.z;

    const __nv_bfloat16* Qb = Qg + (size_t)(b * TT + qt * 128) * DIM + h * HD;
    const __nv_bfloat16* Kb = Kg + (size_t)(b * TT) * DIM + h * HD;
    const __nv_bfloat16* Vb = Vg + (size_t)(b * TT) * DIM + h * HD;

    #pragma unroll
    for (int t = 0; t < 8; t++) {
        int ch = tid + t * 256;
        int row = ch >> 4, c16 = ch & 15;
        uint32_t dst = sQ + row * 272 + c16 * 16;
        const __nv_bfloat16* src = Qb + (size_t)row * DIM + c16 * 8;
        asm volatile("cp.async.cg.shared.global [%0], [%1], 16;" :: "r"(dst), "l"(src) : "memory");
    }
    asm volatile("cp.async.commit_group;" ::: "memory");

    auto loadKV = [&](int kt, int stage) {
        uint32_t base = sKV + stage * KV_BYTES;
        const __nv_bfloat16* Kt = Kb + (size_t)kt * 64 * DIM;
        const __nv_bfloat16* Vt = Vb + (size_t)kt * 64 * DIM;
        #pragma unroll
        for (int t = 0; t < 8; t++) {
            int ch = tid + t * 256;
            int row = (ch >> 4) & 63, c16 = ch & 15;
            bool isV = ch >= 1024;
            const __nv_bfloat16* src = (isV ? Vt : Kt) + (size_t)row * DIM + c16 * 8;
            uint32_t dst = base + (isV ? (64u * 272u) : 0u) + row * 272 + c16 * 16;
            asm volatile("cp.async.cg.shared.global [%0], [%1], 16;" :: "r"(dst), "l"(src) : "memory");
        }
        asm volatile("cp.async.commit_group;" ::: "memory");
    };

    const int numK = 2 * qt + 2;
    loadKV(0, 0);
    loadKV(1, 1);

    float oacc[16][4];
    #pragma unroll
    for (int j = 0; j < 16; j++)
        #pragma unroll
        for (int q = 0; q < 4; q++) oacc[j][q] = 0.f;
    float den0 = 0.f, den1 = 0.f;

    const int rowadd = (lane & 7) + ((lane >> 3) & 1) * 8;
    const int colmi  = (lane >> 4) * 16;
    const int colq   = (lane & 3) * 2;
    const int rr0    = qt * 128 + w * 16 + (lane >> 2);

    #pragma unroll 1
    for (int kt = 0; kt < numK; kt++) {
        asm volatile("cp.async.wait_group %0;" :: "n"(1));
        __syncthreads();
        const uint32_t sK = sKV + (kt & 1) * KV_BYTES;
        const uint32_t sV = sK + 64u * 272u;

        float cs[8][4];
        #pragma unroll
        for (int j = 0; j < 8; j++)
            #pragma unroll
            for (int q = 0; q < 4; q++) cs[j][q] = 0.f;

        #pragma unroll
        for (int s = 0; s < 8; s++) {
            uint32_t a0, a1, a2, a3;
            LDSM_X4(a0, a1, a2, a3, sQ + (w * 16 + rowadd) * 272 + s * 32 + colmi);
            #pragma unroll
            for (int g = 0; g < 4; g++) {
                uint32_t k0, k1, k2, k3;
                LDSM_X4(k0, k1, k2, k3, sK + (g * 16 + rowadd) * 272 + s * 32 + colmi);
                MMA_BF16(cs[2*g],   a0, a1, a2, a3, k0, k2);
                MMA_BF16(cs[2*g+1], a0, a1, a2, a3, k1, k3);
            }
        }

        const bool msk = (kt >= 2 * qt);
        #pragma unroll
        for (int j = 0; j < 8; j++) {
            const int cb = kt * 64 + j * 8 + colq;
            #pragma unroll
            for (int q = 0; q < 4; q++) {
                float sv = cs[j][q] * SCALE_QK;
                float xx = sv * (1.0f / SOFTCAP);
                float x2 = xx * xx;
                float capped;
                if (fabsf(xx) > 0.55f) capped = SOFTCAP * tanhf(xx);
                else capped = sv * (1.0f - x2 * (0.33333334f - x2 * (0.13333334f - x2 * 0.05396825f)));
                float p = __expf(capped);
                if (msk) {
                    int col = cb + (q & 1);
                    int rowg = rr0 + (q >> 1) * 8;
                    if (col > rowg) p = 0.f;
                }
                cs[j][q] = p;
                if (q >> 1) den1 += p; else den0 += p;
            }
        }

        uint32_t pa[4][4];
        #pragma unroll
        for (int kk = 0; kk < 4; kk++) {
            pa[kk][0] = packbf(cs[2*kk][0],   cs[2*kk][1]);
            pa[kk][1] = packbf(cs[2*kk][2],   cs[2*kk][3]);
            pa[kk][2] = packbf(cs[2*kk+1][0], cs[2*kk+1][1]);
            pa[kk][3] = packbf(cs[2*kk+1][2], cs[2*kk+1][3]);
        }

        #pragma unroll
        for (int kk = 0; kk < 4; kk++) {
            #pragma unroll
            for (int g = 0; g < 8; g++) {
                uint32_t v0, v1, v2, v3;
                LDSM_X4_T(v0, v1, v2, v3, sV + (kk * 16 + rowadd) * 272 + g * 32 + colmi);
                MMA_BF16(oacc[2*g],   pa[kk][0], pa[kk][1], pa[kk][2], pa[kk][3], v0, v1);
                MMA_BF16(oacc[2*g+1], pa[kk][0], pa[kk][1], pa[kk][2], pa[kk][3], v2, v3);
            }
        }

        __syncthreads();
        if (kt + 2 < numK) loadKV(kt + 2, kt & 1);
        else asm volatile("cp.async.commit_group;" ::: "memory");
    }

    den0 += __shfl_xor_sync(0xffffffffu, den0, 1);
    den0 += __shfl_xor_sync(0xffffffffu, den0, 2);
    den1 += __shfl_xor_sync(0xffffffffu, den1, 1);
    den1 += __shfl_xor_sync(0xffffffffu, den1, 2);
    const float i0 = 1.0f / den0, i1 = 1.0f / den1;

    // epilogue: split-bf16 write to g_at2 ([hi|lo], row stride K2)
    const int t0 = qt * 128 + w * 16 + (lane >> 2);
    unsigned short* outb = (unsigned short*)g_at2;
    size_t base0 = ((size_t)(b * TT + t0)) * K2 + h * 128 + colq;
    size_t base1 = base0 + (size_t)8 * K2;
    #pragma unroll
    for (int j = 0; j < 16; j++) {
        float p0 = oacc[j][0] * i0, p1 = oacc[j][1] * i0;
        float p2 = oacc[j][2] * i1, p3 = oacc[j][3] * i1;
        unsigned short h0, l0, h1, l1, h2, l2, h3, l3;
        bsplit(p0, h0, l0); bsplit(p1, h1, l1);
        bsplit(p2, h2, l2); bsplit(p3, h3, l3);
        unsigned short* q0 = outb + base0 + j * 8;
        unsigned short* q1 = outb + base1 + j * 8;
        *(ushort2*)(q0)        = make_ushort2(h0, h1);
        *(ushort2*)(q0 + 2048) = make_ushort2(l0, l1);
        *(ushort2*)(q1)        = make_ushort2(h2, h3);
        *(ushort2*)(q1 + 2048) = make_ushort2(l2, l3);
    }
}

// ---------------------------- gate + residual blend ---------------------------
__global__ __launch_bounds__(256)
void blend_kernel(const float* __restrict__ x, const float* __restrict__ gb,
                  float* __restrict__ out)
{
    const int i4 = blockIdx.x * 256 + threadIdx.x;
    const int col4 = i4 & 511;
    float4 xv = ((const float4*)x)[i4];
    float4 ov = ((const float4*)g_op)[i4];
    float4 gv = ((const float4*)g_gl)[i4];
    float4 bv = ((const float4*)gb)[col4];
    float a0 = 1.0f / (1.0f + __expf(-(gv.x + bv.x)));
    float a1 = 1.0f / (1.0f + __expf(-(gv.y + bv.y)));
    float a2 = 1.0f / (1.0f + __expf(-(gv.z + bv.z)));
    float a3 = 1.0f / (1.0f + __expf(-(gv.w + bv.w)));
    float4 r;
    r.x = xv.x + a0 * (ov.x - xv.x);
    r.y = xv.y + a1 * (ov.y - xv.y);
    r.z = xv.z + a2 * (ov.z - xv.z);
    r.w = xv.w + a3 * (ov.w - xv.w);
    ((float4*)out)[i4] = r;
}

// ----------------------------------- launch -----------------------------------
extern "C" void kernel_launch(void* const* d_in, const int* in_sizes, int n_in,
                              void* d_out, int out_size)
{
    (void)in_sizes; (void)n_in; (void)out_size;
    const float* x   = (const float*)d_in[0];
    const float* Wq  = (const float*)d_in[2];
    const float* Wk  = (const float*)d_in[3];
    const float* Wv  = (const float*)d_in[4];
    const float* Wo  = (const float*)d_in[5];
    const float* lnw = (const float*)d_in[6];
    const float* gW  = (const float*)d_in[7];
    const float* gb  = (const float*)d_in[8];
    float* out = (float*)d_out;

    static int attr_set = 0;
    static cudaStream_t s1 = nullptr;
    static cudaEvent_t evFork = nullptr, evJoin = nullptr, evQKV = nullptr,
                       evConv = nullptr, evWb = nullptr;
    if (!attr_set) {
        cudaFuncSetAttribute(mma_gemm3_kernel,    cudaFuncAttributeMaxDynamicSharedMemorySize, GEMM_SMEM);
        cudaFuncSetAttribute(mma_gemm_qkv_kernel, cudaFuncAttributeMaxDynamicSharedMemorySize, GEMM_SMEM);
        cudaFuncSetAttribute(attn_mma_kernel,     cudaFuncAttributeMaxDynamicSharedMemorySize, ATT2_SMEM);
        cudaStreamCreateWithFlags(&s1, cudaStreamNonBlocking);
        cudaEventCreateWithFlags(&evFork, cudaEventDisableTiming);
        cudaEventCreateWithFlags(&evJoin, cudaEventDisableTiming);
        cudaEventCreateWithFlags(&evQKV, cudaEventDisableTiming);
        cudaEventCreateWithFlags(&evConv, cudaEventDisableTiming);
        cudaEventCreateWithFlags(&evWb, cudaEventDisableTiming);
        attr_set = 1;
    }

    void *pop, *pgl, *px2, *pat2, *pw3, *pqb, *pkb, *pvb;
    cudaGetSymbolAddress(&pop, g_op);
    cudaGetSymbolAddress(&pgl, g_gl);
    cudaGetSymbolAddress(&px2,  g_x2);
    cudaGetSymbolAddress(&pat2, g_at2);
    cudaGetSymbolAddress(&pw3,  g_w3);
    cudaGetSymbolAddress(&pqb, g_qb);
    cudaGetSymbolAddress(&pkb, g_kb);
    cudaGetSymbolAddress(&pvb, g_vb);
    __nv_bfloat16* w3 = (__nv_bfloat16*)pw3;
    const size_t WSTRIDE3 = (size_t)DIM * K3;

    dim3 gGemm(DIM / BN, MTOT / BM);        // (16, 32)

    // ---- fork side stream: convert_wb first (QKV dep), then x2/gW/Wo converts ----
    cudaEventRecord(evFork, 0);
    cudaStreamWaitEvent(s1, evFork, 0);

    dim3 gWb((DIM * (DIM/4)) / 256, 3);
    convert_wb_kernel<<<gWb, 256, 0, s1>>>(Wq, Wk, Wv);
    cudaEventRecord(evWb, s1);
    convert_split2_kernel<<<(MTOT * (DIM/4)) / 256, 256, 0, s1>>>(x, (__nv_bfloat16*)px2);
    convert_split3_kernel<<<(DIM  * (DIM/4)) / 256, 256, 0, s1>>>(gW, w3 + 1 * WSTRIDE3);
    convert_split3_kernel<<<(DIM  * (DIM/4)) / 256, 256, 0, s1>>>(Wo, w3 + 0 * WSTRIDE3);
    cudaEventRecord(evConv, s1);

    // ---- main stream: rmsnorm (|| convert_wb) -> QKV GEMM (uncontended) ----
    rmsnorm_bf16_kernel<<<MTOT, 256>>>(x, lnw);
    cudaStreamWaitEvent(0, evWb, 0);

    dim3 gQKV(DIM / BN, MTOT / BM, 3);      // (16, 32, 3)
    mma_gemm_qkv_kernel<<<gQKV, 256, GEMM_SMEM>>>();
    cudaEventRecord(evQKV, 0);

    // ---- s1: gate GEMM overlapping attention (low-tensor window) ----
    cudaStreamWaitEvent(s1, evQKV, 0);
    mma_gemm3_kernel<<<gGemm, 256, GEMM_SMEM, s1>>>((const __nv_bfloat16*)px2, w3 + 1 * WSTRIDE3, (float*)pgl, DIM);
    cudaEventRecord(evJoin, s1);

    // ---- main stream: attention -> Wo GEMM ----
    dim3 gAttn(TT / 128, NH, BB);           // (16, 16, 2)
    attn_mma_kernel<<<gAttn, 256, ATT2_SMEM>>>((const __nv_bfloat16*)pqb,
                                               (const __nv_bfloat16*)pkb,
                                               (const __nv_bfloat16*)pvb);

    cudaStreamWaitEvent(0, evConv, 0);
    mma_gemm3_kernel<<<gGemm, 256, GEMM_SMEM>>>((const __nv_bfloat16*)pat2, w3 + 0 * WSTRIDE3, (float*)pop, DIM);

    cudaStreamWaitEvent(0, evJoin, 0);
    blend_kernel<<<(MTOT * DIM / 4) / 256, 256>>>(x, gb, out);
}